// round 14
// baseline (speedup 1.0000x reference)
#include <cuda_runtime.h>
#include <cuda_fp16.h>

#define HH 128
#define WW 128
#define BB 64
#define OO 32
#define NPIX (HH * WW)
#define TPB 256

// swizzle for the result plane: conflict-free for STS (any swz), for writeout
// (x=4l+k -> bank p^l^8k, permutation in l), covers all 128 x.
__device__ __forceinline__ int swz(int x) { return ((x >> 2) ^ ((x & 3) << 3)) & 31; }

// 8 MB quad tap table: g_Q[pix][lane(b-pair)] = {Ia, Ic, Ib, Id} as 4x half2
//   Ia=(x,y) Ic=(x+1,y) Ib=(x,y+1) Id=(x+1,y+1), neighbors clamped to edge
__device__ uint4 g_Q[NPIX * 32];
__device__ float4 g_aff[OO];
__device__ float2 g_off[OO];

// grid = HH*4 + 1 blocks of 256.  bid < HH*4: y = bid>>2, x-quadrant q = bid&3.
__global__ __launch_bounds__(256) void build_kernel(
    const float* __restrict__ X,
    const float* __restrict__ eps,
    const float* __restrict__ tmin,
    const float* __restrict__ tmax)
{
    const int bid = blockIdx.x;
    if (bid == HH * 4) {                    // affine setup block
        const int o = threadIdx.x;
        if (o < OO) {
            float th[7];
            #pragma unroll
            for (int i = 0; i < 7; i++) {
                const float mn = tmin[i];
                th[i] = fmaf(tmax[i] - mn, eps[o * 7 + i], mn);
            }
            float s, c;
            sincosf(th[0], &s, &c);
            const float sx = th[1], sy = th[2], pX = th[3], pY = th[4], tx = th[5], ty = th[6];
            const float a00 = c * sx - s * pY;
            const float a01 = c * pX - s * sy;
            const float a10 = s * sx + c * pY;
            const float a11 = s * pX + c * sy;
            // pixel coords: px = a00*x + a01*y + offx   [(2/127)*63.5 == 1 exactly]
            g_aff[o] = make_float4(a00, a10, a01, a11);
            g_off[o] = make_float2(63.5f * (tx + 1.0f - a00 - a01),
                                   63.5f * (ty + 1.0f - a10 - a11));
        }
        cudaTriggerProgrammaticLaunchCompletion();
        return;
    }

    // staging tile: rows (y, y+1) x local cols [0,33) x 64 b (as 32 b-pairs + pad)
    __shared__ __half2 s2[2][33][33];       // [r][xl][bpair], pad -> conflict-free
    const int y    = bid >> 2;
    const int q    = bid & 3;
    const int yn   = min(y + 1, HH - 1);
    const int lane = threadIdx.x & 31;
    const int warp = threadIdx.x >> 5;      // 0..7

    // stage: 128 (r,b) tasks over 8 warps; unrolled -> 16 LDGs in flight per warp
    #pragma unroll
    for (int t = 0; t < 16; t++) {
        const int task = warp + t * 8;      // 0..127
        const int r = task >> 6;
        const int b = task & (BB - 1);
        const float* src = X + ((size_t)b * HH + (r ? yn : y)) * WW;
        __half* hp = reinterpret_cast<__half*>(&s2[r][0][b >> 1]) + (b & 1);
        const int gx = min(q * 32 + lane, WW - 1);
        hp[lane * 66] = __float2half(src[gx]);
        if (lane == 0) {
            const int gx2 = min(q * 32 + 32, WW - 1);
            hp[32 * 66] = __float2half(src[gx2]);
        }
    }
    __syncthreads();

    // emit quad records: warp handles xl = 4w..4w+3; lane = b-pair
    uint4* dst = g_Q + ((size_t)y * WW + q * 32) * 32;
    #pragma unroll
    for (int ii = 0; ii < 4; ii++) {
        const int xl = warp * 4 + ii;
        uint4 qq;
        qq.x = *reinterpret_cast<const unsigned*>(&s2[0][xl][lane]);
        qq.y = *reinterpret_cast<const unsigned*>(&s2[0][xl + 1][lane]);
        qq.z = *reinterpret_cast<const unsigned*>(&s2[1][xl][lane]);
        qq.w = *reinterpret_cast<const unsigned*>(&s2[1][xl + 1][lane]);
        dst[xl * 32 + lane] = qq;           // 512B contiguous per warp
    }
    cudaTriggerProgrammaticLaunchCompletion();
}

__global__ __launch_bounds__(TPB, 6) void dalayer_kernel(float* __restrict__ out)
{
    // swizzled half2 plane: [x][col] holds b-pair (col ^ swz(x))
    __shared__ __half2 plane[WW][32];       // 16 KB

    const int tid  = threadIdx.x;
    const int lane = tid & 31;
    const int warp = tid >> 5;              // 0..7
    const int y = blockIdx.x;
    const int o = blockIdx.y;

    // wait for build_kernel's g_aff/g_off/g_Q to be visible (PDL dependency)
    cudaGridDependencySynchronize();

    const float4 A  = g_aff[o];
    const float2 Of = g_off[o];
    const float a00 = A.x, a10 = A.y, a01 = A.z, a11 = A.w;

    const float rowx = fmaf(a01, (float)y, Of.x);
    const float rowy = fmaf(a11, (float)y, Of.y);

    // ---- compute: warp w handles x = 16w..16w+15, in 4 groups of 4 (MLP=4) ----
    #pragma unroll
    for (int g = 0; g < 4; g++) {
        uint4   qv[4];
        __half2 wx2[4], wy2[4];

        #pragma unroll
        for (int k = 0; k < 4; k++) {
            const int x = warp * 16 + g * 4 + k;
            const float cx = fminf(fmaxf(fmaf(a00, (float)x, rowx), 0.0f), 126.99999f);
            const float cy = fminf(fmaxf(fmaf(a10, (float)x, rowy), 0.0f), 126.99999f);
            const int x0 = (int)cx;
            const int y0 = (int)cy;
            wx2[k] = __float2half2_rn(cx - (float)x0);
            wy2[k] = __float2half2_rn(cy - (float)y0);
            qv[k] = g_Q[(unsigned)((y0 * WW + x0) * 32 + lane)];  // 4 LDG.128 in flight
        }

        #pragma unroll
        for (int k = 0; k < 4; k++) {
            const int x = warp * 16 + g * 4 + k;
            const __half2 Ia = *reinterpret_cast<const __half2*>(&qv[k].x);
            const __half2 Ic = *reinterpret_cast<const __half2*>(&qv[k].y);
            const __half2 Ib = *reinterpret_cast<const __half2*>(&qv[k].z);
            const __half2 Id = *reinterpret_cast<const __half2*>(&qv[k].w);

            const __half2 t0 = __hfma2(wx2[k], __hsub2(Ic, Ia), Ia);
            const __half2 t1 = __hfma2(wx2[k], __hsub2(Id, Ib), Ib);
            const __half2 r  = __hfma2(wy2[k], __hsub2(t1, t0), t0);

            plane[x][lane ^ swz(x)] = r;     // bank = lane^const: conflict-free
        }
    }

    __syncthreads();

    // ---- writeout: warp w handles b-pairs p = 4w..4w+3; lane owns x = 4l..4l+3 ----
    #pragma unroll
    for (int pp = 0; pp < 4; pp++) {
        const int p = warp * 4 + pp;         // b = 2p, 2p+1
        float4 lo, hi;
        {
            // bank(k) = p ^ lane ^ 8k: permutation over lanes for each k
            const float2 v0 = __half22float2(plane[4 * lane + 0][p ^ lane ^ 0]);
            const float2 v1 = __half22float2(plane[4 * lane + 1][p ^ lane ^ 8]);
            const float2 v2 = __half22float2(plane[4 * lane + 2][p ^ lane ^ 16]);
            const float2 v3 = __half22float2(plane[4 * lane + 3][p ^ lane ^ 24]);
            lo = make_float4(v0.x, v1.x, v2.x, v3.x);
            hi = make_float4(v0.y, v1.y, v2.y, v3.y);
        }
        float* __restrict__ d0 = out + (size_t)(o * BB + 2 * p) * NPIX + y * WW;
        reinterpret_cast<float4*>(d0)[lane]        = lo;   // STG.128, coalesced
        reinterpret_cast<float4*>(d0 + NPIX)[lane] = hi;
    }
}

extern "C" void kernel_launch(void* const* d_in, const int* in_sizes, int n_in,
                              void* d_out, int out_size)
{
    const float* X    = (const float*)d_in[0];
    const float* eps  = (const float*)d_in[1];
    const float* tmin = (const float*)d_in[2];
    const float* tmax = (const float*)d_in[3];
    float* out = (float*)d_out;

    build_kernel<<<HH * 4 + 1, 256>>>(X, eps, tmin, tmax);

    // main kernel with programmatic dependent launch: overlaps launch latency
    // with build's tail; cudaGridDependencySynchronize() gates data reads.
    cudaLaunchConfig_t cfg = {};
    cfg.gridDim  = dim3(HH, OO);
    cfg.blockDim = dim3(TPB);
    cudaLaunchAttribute attrs[1];
    attrs[0].id = cudaLaunchAttributeProgrammaticStreamSerialization;
    attrs[0].val.programmaticStreamSerializationAllowed = 1;
    cfg.attrs = attrs;
    cfg.numAttrs = 1;
    cudaLaunchKernelEx(&cfg, dalayer_kernel, out);
}

// round 15
// speedup vs baseline: 1.0563x; 1.0563x over previous
#include <cuda_runtime.h>
#include <cuda_fp16.h>

#define HH 128
#define WW 128
#define BB 64
#define OO 32
#define NPIX (HH * WW)
#define TPB 256
#define NQBLK (HH * 4)           // g_Q builder blocks
#define NWBLK ((OO * NPIX) / 256) // g_W builder blocks = 2048

// 8 MB quad tap table: g_Q[pix][lane(b-pair)] = {Ia, Ic, Ib, Id} as 4x half2
//   Ia=(x,y) Ic=(x+1,y) Ib=(x,y+1) Id=(x+1,y+1), neighbors clamped to edge
__device__ uint4 g_Q[NPIX * 32];
// 4 MB coord table: g_W[(o*HH+y)*WW+x] = { y0*128+x0, half2(wx, wy) }
__device__ uint2 g_W[OO * NPIX];

// grid = NQBLK + NWBLK blocks of 256.
__global__ __launch_bounds__(256) void build_kernel(
    const float* __restrict__ X,
    const float* __restrict__ eps,
    const float* __restrict__ tmin,
    const float* __restrict__ tmax)
{
    const int bid = blockIdx.x;

    if (bid >= NQBLK) {                     // ---- g_W builder: one (o,y,x) per thread
        const int t = (bid - NQBLK) * 256 + threadIdx.x;   // 0..524287
        const int o = t >> 14;
        const int y = (t >> 7) & (HH - 1);
        const int x = t & (WW - 1);

        float th[7];
        #pragma unroll
        for (int i = 0; i < 7; i++) {
            const float mn = tmin[i];
            th[i] = fmaf(tmax[i] - mn, eps[o * 7 + i], mn);
        }
        float s, c;
        sincosf(th[0], &s, &c);
        const float sx = th[1], sy = th[2], pX = th[3], pY = th[4], tx = th[5], ty = th[6];
        const float a00 = c * sx - s * pY;
        const float a01 = c * pX - s * sy;
        const float a10 = s * sx + c * pY;
        const float a11 = s * pX + c * sy;
        // pixel coords: px = a00*x + a01*y + offx   [(2/127)*63.5 == 1 exactly]
        const float offx = 63.5f * (tx + 1.0f - a00 - a01);
        const float offy = 63.5f * (ty + 1.0f - a10 - a11);

        const float px = fmaf(a00, (float)x, fmaf(a01, (float)y, offx));
        const float py = fmaf(a10, (float)x, fmaf(a11, (float)y, offy));
        const float cx = fminf(fmaxf(px, 0.0f), 126.99999f);
        const float cy = fminf(fmaxf(py, 0.0f), 126.99999f);
        const int x0 = (int)cx;
        const int y0 = (int)cy;
        const __half2 w2 = __floats2half2_rn(cx - (float)x0, cy - (float)y0);

        uint2 rec;
        rec.x = (unsigned)(y0 * WW + x0);
        rec.y = *reinterpret_cast<const unsigned*>(&w2);
        g_W[t] = rec;                        // coalesced
        cudaTriggerProgrammaticLaunchCompletion();
        return;
    }

    // ---- g_Q builder (proven): y = bid>>2, x-quadrant q = bid&3 ----
    __shared__ __half2 s2[2][33][33];       // [r][xl][bpair], pad -> conflict-free
    const int y    = bid >> 2;
    const int q    = bid & 3;
    const int yn   = min(y + 1, HH - 1);
    const int lane = threadIdx.x & 31;
    const int warp = threadIdx.x >> 5;      // 0..7

    #pragma unroll
    for (int t = 0; t < 16; t++) {
        const int task = warp + t * 8;      // 0..127
        const int r = task >> 6;
        const int b = task & (BB - 1);
        const float* src = X + ((size_t)b * HH + (r ? yn : y)) * WW;
        __half* hp = reinterpret_cast<__half*>(&s2[r][0][b >> 1]) + (b & 1);
        const int gx = min(q * 32 + lane, WW - 1);
        hp[lane * 66] = __float2half(src[gx]);
        if (lane == 0) {
            const int gx2 = min(q * 32 + 32, WW - 1);
            hp[32 * 66] = __float2half(src[gx2]);
        }
    }
    __syncthreads();

    uint4* dst = g_Q + ((size_t)y * WW + q * 32) * 32;
    #pragma unroll
    for (int ii = 0; ii < 4; ii++) {
        const int xl = warp * 4 + ii;
        uint4 qq;
        qq.x = *reinterpret_cast<const unsigned*>(&s2[0][xl][lane]);
        qq.y = *reinterpret_cast<const unsigned*>(&s2[0][xl + 1][lane]);
        qq.z = *reinterpret_cast<const unsigned*>(&s2[1][xl][lane]);
        qq.w = *reinterpret_cast<const unsigned*>(&s2[1][xl + 1][lane]);
        dst[xl * 32 + lane] = qq;           // 512B contiguous per warp
    }
    cudaTriggerProgrammaticLaunchCompletion();
}

__global__ __launch_bounds__(TPB, 8) void dalayer_kernel(float* __restrict__ out)
{
    // swizzled half2 plane: [x][col] holds b-pair (col ^ (x&31))
    __shared__ __half2 plane[WW][32];       // 16 KB

    const int tid  = threadIdx.x;
    const int lane = tid & 31;
    const int warp = tid >> 5;              // 0..7
    const int y = blockIdx.x;
    const int o = blockIdx.y;

    // wait for build_kernel's g_W/g_Q to be visible (PDL dependency)
    cudaGridDependencySynchronize();

    // lanes 0..15 fetch this warp's 16 precomputed coord records in ONE LDG.64
    const unsigned base = (unsigned)((o * HH + y) * WW + warp * 16);
    uint2 w = g_W[base + (lane & 15)];

    // ---- compute: warp w handles x = 16w..16w+15; lane = b-pair ----
    #pragma unroll
    for (int i = 0; i < 16; i++) {
        const unsigned idx = __shfl_sync(0xffffffffu, w.x, i);
        const unsigned whb = __shfl_sync(0xffffffffu, w.y, i);

        const uint4 qv = g_Q[idx * 32 + lane];    // ONE LDG.128: all 4 taps

        const __half2 wb  = *reinterpret_cast<const __half2*>(&whb);
        const __half2 wx2 = __half2half2(__low2half(wb));
        const __half2 wy2 = __half2half2(__high2half(wb));

        const __half2 Ia = *reinterpret_cast<const __half2*>(&qv.x);
        const __half2 Ic = *reinterpret_cast<const __half2*>(&qv.y);
        const __half2 Ib = *reinterpret_cast<const __half2*>(&qv.z);
        const __half2 Id = *reinterpret_cast<const __half2*>(&qv.w);

        const __half2 t0 = __hfma2(wx2, __hsub2(Ic, Ia), Ia);
        const __half2 t1 = __hfma2(wx2, __hsub2(Id, Ib), Ib);
        const __half2 r  = __hfma2(wy2, __hsub2(t1, t0), t0);

        const int x = warp * 16 + i;
        plane[x][lane ^ (x & 31)] = r;       // bank permutation: conflict-free
    }

    __syncthreads();

    // ---- writeout: warp w handles b-pairs p = 4w..4w+3; lane = x mod 32 ----
    #pragma unroll
    for (int pp = 0; pp < 4; pp++) {
        const int p = warp * 4 + pp;         // b = 2p, 2p+1
        float* __restrict__ d0 = out + (size_t)(o * BB + 2 * p) * NPIX + y * WW;
        float* __restrict__ d1 = d0 + NPIX;
        #pragma unroll
        for (int j = 0; j < 4; j++) {
            const int x = j * 32 + lane;
            const float2 v = __half22float2(plane[x][p ^ lane]); // bank perm: conflict-free
            d0[x] = v.x;
            d1[x] = v.y;
        }
    }
}

extern "C" void kernel_launch(void* const* d_in, const int* in_sizes, int n_in,
                              void* d_out, int out_size)
{
    const float* X    = (const float*)d_in[0];
    const float* eps  = (const float*)d_in[1];
    const float* tmin = (const float*)d_in[2];
    const float* tmax = (const float*)d_in[3];
    float* out = (float*)d_out;

    build_kernel<<<NQBLK + NWBLK, 256>>>(X, eps, tmin, tmax);

    // main kernel with programmatic dependent launch: overlaps launch latency
    // with build's tail; cudaGridDependencySynchronize() gates data reads.
    cudaLaunchConfig_t cfg = {};
    cfg.gridDim  = dim3(HH, OO);
    cfg.blockDim = dim3(TPB);
    cudaLaunchAttribute attrs[1];
    attrs[0].id = cudaLaunchAttributeProgrammaticStreamSerialization;
    attrs[0].val.programmaticStreamSerializationAllowed = 1;
    cfg.attrs = attrs;
    cfg.numAttrs = 1;
    cudaLaunchKernelEx(&cfg, dalayer_kernel, out);
}

// round 16
// speedup vs baseline: 1.0623x; 1.0057x over previous
#include <cuda_runtime.h>
#include <cuda_fp16.h>

#define HH 128
#define WW 128
#define BB 64
#define OO 32
#define NPIX (HH * WW)
#define TPB 256
#define NQBLK (HH * 4)            // g_Q builder blocks
#define NWBLK ((OO * NPIX) / 256) // g_W builder blocks = 2048

// plane swizzle: col = lane ^ swz(x).  swz(4l+k) = l ^ (k<<3)  (l<32, k<4)
__device__ __forceinline__ int swz(int x) { return ((x >> 2) ^ ((x & 3) << 3)) & 31; }

// 8 MB quad tap table: g_Q[pix][lane(b-pair)] = {Ia, Ic, Ib, Id} as 4x half2
//   Ia=(x,y) Ic=(x+1,y) Ib=(x,y+1) Id=(x+1,y+1), neighbors clamped to edge
__device__ uint4 g_Q[NPIX * 32];
// 4 MB coord table: g_W[(o*HH+y)*WW+x] = { y0*128+x0, half2(wx, wy) }
__device__ uint2 g_W[OO * NPIX];

// grid = NQBLK + NWBLK blocks of 256.
__global__ __launch_bounds__(256) void build_kernel(
    const float* __restrict__ X,
    const float* __restrict__ eps,
    const float* __restrict__ tmin,
    const float* __restrict__ tmax)
{
    const int bid = blockIdx.x;

    if (bid >= NQBLK) {                     // ---- g_W builder: 256 (y,x) of one o per block
        __shared__ float sA[6];             // a00 a10 a01 a11 offx offy
        const int t0i = (bid - NQBLK) * 256;
        const int o   = t0i >> 14;          // constant within block

        if (threadIdx.x == 0) {             // affine once per block
            float th[7];
            #pragma unroll
            for (int i = 0; i < 7; i++) {
                const float mn = tmin[i];
                th[i] = fmaf(tmax[i] - mn, eps[o * 7 + i], mn);
            }
            float s, c;
            sincosf(th[0], &s, &c);
            const float sx = th[1], sy = th[2], pX = th[3], pY = th[4], tx = th[5], ty = th[6];
            const float a00 = c * sx - s * pY;
            const float a01 = c * pX - s * sy;
            const float a10 = s * sx + c * pY;
            const float a11 = s * pX + c * sy;
            sA[0] = a00; sA[1] = a10; sA[2] = a01; sA[3] = a11;
            // pixel coords: px = a00*x + a01*y + offx   [(2/127)*63.5 == 1 exactly]
            sA[4] = 63.5f * (tx + 1.0f - a00 - a01);
            sA[5] = 63.5f * (ty + 1.0f - a10 - a11);
        }
        __syncthreads();

        const int t = t0i + threadIdx.x;
        const int y = (t >> 7) & (HH - 1);
        const int x = t & (WW - 1);

        const float px = fmaf(sA[0], (float)x, fmaf(sA[2], (float)y, sA[4]));
        const float py = fmaf(sA[1], (float)x, fmaf(sA[3], (float)y, sA[5]));
        const float cx = fminf(fmaxf(px, 0.0f), 126.99999f);
        const float cy = fminf(fmaxf(py, 0.0f), 126.99999f);
        const int x0 = (int)cx;
        const int y0 = (int)cy;
        const __half2 w2 = __floats2half2_rn(cx - (float)x0, cy - (float)y0);

        uint2 rec;
        rec.x = (unsigned)(y0 * WW + x0);
        rec.y = *reinterpret_cast<const unsigned*>(&w2);
        g_W[t] = rec;                        // coalesced
        cudaTriggerProgrammaticLaunchCompletion();
        return;
    }

    // ---- g_Q builder (proven): y = bid>>2, x-quadrant q = bid&3 ----
    __shared__ __half2 s2[2][33][33];       // [r][xl][bpair], pad -> conflict-free
    const int y    = bid >> 2;
    const int q    = bid & 3;
    const int yn   = min(y + 1, HH - 1);
    const int lane = threadIdx.x & 31;
    const int warp = threadIdx.x >> 5;      // 0..7

    #pragma unroll
    for (int t = 0; t < 16; t++) {
        const int task = warp + t * 8;      // 0..127
        const int r = task >> 6;
        const int b = task & (BB - 1);
        const float* src = X + ((size_t)b * HH + (r ? yn : y)) * WW;
        __half* hp = reinterpret_cast<__half*>(&s2[r][0][b >> 1]) + (b & 1);
        const int gx = min(q * 32 + lane, WW - 1);
        hp[lane * 66] = __float2half(src[gx]);
        if (lane == 0) {
            const int gx2 = min(q * 32 + 32, WW - 1);
            hp[32 * 66] = __float2half(src[gx2]);
        }
    }
    __syncthreads();

    uint4* dst = g_Q + ((size_t)y * WW + q * 32) * 32;
    #pragma unroll
    for (int ii = 0; ii < 4; ii++) {
        const int xl = warp * 4 + ii;
        uint4 qq;
        qq.x = *reinterpret_cast<const unsigned*>(&s2[0][xl][lane]);
        qq.y = *reinterpret_cast<const unsigned*>(&s2[0][xl + 1][lane]);
        qq.z = *reinterpret_cast<const unsigned*>(&s2[1][xl][lane]);
        qq.w = *reinterpret_cast<const unsigned*>(&s2[1][xl + 1][lane]);
        dst[xl * 32 + lane] = qq;           // 512B contiguous per warp
    }
    cudaTriggerProgrammaticLaunchCompletion();
}

__global__ __launch_bounds__(TPB, 8) void dalayer_kernel(float* __restrict__ out)
{
    // swizzled half2 plane: [x][col] holds b-pair (col ^ swz(x))
    __shared__ __half2 plane[WW][32];       // 16 KB

    const int tid  = threadIdx.x;
    const int lane = tid & 31;
    const int warp = tid >> 5;              // 0..7
    const int y = blockIdx.x;
    const int o = blockIdx.y;

    // wait for build_kernel's g_W/g_Q to be visible (PDL dependency)
    cudaGridDependencySynchronize();

    // lanes 0..15 fetch this warp's 16 precomputed coord records in ONE LDG.64
    const unsigned base = (unsigned)((o * HH + y) * WW + warp * 16);
    uint2 w = g_W[base + (lane & 15)];

    // ---- compute: warp w handles x = 16w..16w+15; lane = b-pair ----
    #pragma unroll
    for (int i = 0; i < 16; i++) {
        const unsigned idx = __shfl_sync(0xffffffffu, w.x, i);
        const unsigned whb = __shfl_sync(0xffffffffu, w.y, i);

        const uint4 qv = g_Q[idx * 32 + lane];    // ONE LDG.128: all 4 taps

        const __half2 wb  = *reinterpret_cast<const __half2*>(&whb);
        const __half2 wx2 = __half2half2(__low2half(wb));
        const __half2 wy2 = __half2half2(__high2half(wb));

        const __half2 Ia = *reinterpret_cast<const __half2*>(&qv.x);
        const __half2 Ic = *reinterpret_cast<const __half2*>(&qv.y);
        const __half2 Ib = *reinterpret_cast<const __half2*>(&qv.z);
        const __half2 Id = *reinterpret_cast<const __half2*>(&qv.w);

        const __half2 t0 = __hfma2(wx2, __hsub2(Ic, Ia), Ia);
        const __half2 t1 = __hfma2(wx2, __hsub2(Id, Ib), Ib);
        const __half2 r  = __hfma2(wy2, __hsub2(t1, t0), t0);

        const int x = warp * 16 + i;
        plane[x][lane ^ swz(x)] = r;         // bank permutation: conflict-free
    }

    __syncthreads();

    // ---- writeout: warp w handles b-pairs p = 4w..4w+3; lane owns x = 4l..4l+3 ----
    #pragma unroll
    for (int pp = 0; pp < 4; pp++) {
        const int p = warp * 4 + pp;         // b = 2p, 2p+1
        float4 lo, hi;
        {
            // stored col for (p, x=4l+k) = p ^ swz(4l+k) = p ^ l ^ (k<<3)
            // bank over lanes = permutation for each k -> conflict-free
            const float2 v0 = __half22float2(plane[4 * lane + 0][p ^ lane ^ 0]);
            const float2 v1 = __half22float2(plane[4 * lane + 1][p ^ lane ^ 8]);
            const float2 v2 = __half22float2(plane[4 * lane + 2][p ^ lane ^ 16]);
            const float2 v3 = __half22float2(plane[4 * lane + 3][p ^ lane ^ 24]);
            lo = make_float4(v0.x, v1.x, v2.x, v3.x);
            hi = make_float4(v0.y, v1.y, v2.y, v3.y);
        }
        float* __restrict__ d0 = out + (size_t)(o * BB + 2 * p) * NPIX + y * WW;
        reinterpret_cast<float4*>(d0)[lane]        = lo;   // STG.128, coalesced
        reinterpret_cast<float4*>(d0 + NPIX)[lane] = hi;
    }
}

extern "C" void kernel_launch(void* const* d_in, const int* in_sizes, int n_in,
                              void* d_out, int out_size)
{
    const float* X    = (const float*)d_in[0];
    const float* eps  = (const float*)d_in[1];
    const float* tmin = (const float*)d_in[2];
    const float* tmax = (const float*)d_in[3];
    float* out = (float*)d_out;

    build_kernel<<<NQBLK + NWBLK, 256>>>(X, eps, tmin, tmax);

    // main kernel with programmatic dependent launch: overlaps launch latency
    // with build's tail; cudaGridDependencySynchronize() gates data reads.
    cudaLaunchConfig_t cfg = {};
    cfg.gridDim  = dim3(HH, OO);
    cfg.blockDim = dim3(TPB);
    cudaLaunchAttribute attrs[1];
    attrs[0].id = cudaLaunchAttributeProgrammaticStreamSerialization;
    attrs[0].val.programmaticStreamSerializationAllowed = 1;
    cfg.attrs = attrs;
    cfg.numAttrs = 1;
    cudaLaunchKernelEx(&cfg, dalayer_kernel, out);
}